// round 14
// baseline (speedup 1.0000x reference)
#include <cuda_runtime.h>
#include <cstddef>

// ProdLayer forward: element_mars[nids] = node_mars[cids].sum(axis=1)
//   d_in[0] node_mars     float32  [N_SRC, 128]
//   d_in[1] element_mars  float32  [N_PROD+1, 128]
//   d_in[2] nids          int32    [N_PROD]
//   d_in[3] cids          int32    [N_PROD, 4]
// Output: float32 [N_PROD+1, 128]
//
// FINAL — converged after 13 rounds. Flat launch, warp-per-product,
// float4 lanes: lane l covers float4 column l of each 512 B row; the 4
// child-row gathers are independent LDG.128s (perfectly coalesced, 4x
// 128 B lines per row). __ldcs on index streams + __stcs on the output
// keep write-once/read-once traffic from evicting the randomly
// re-referenced node_mars lines in L2 (the single measurable policy win,
// ~-2%).
//
// Why this is the roofline: traffic is irreducibly ~1.13 GB
//   = 443 MB compulsory gather reads
//   + ~420 MB re-reference misses (L2 hit rate pinned at the 126MB/512MB
//     capacity ratio — the statistical limit for a uniform-random gather)
//   + 256 MB streaming writes + ~10 MB indices,
// sustained at 6.8-6.9 TB/s = 86% of spec HBM — the practical ceiling for
// this read/write mix on GB300. Falsified across R3-R13: column tiling
// (sector-tag amplification), evict_last policies, L1 bypass, LDG.256,
// persistent grids at 47% and 92% occupancy (flat CTA replacement
// pipelines load issue for free; grid-stride loops serialize it), MLP
// depth 4 vs 8, CTA 128 vs 256, index-load reordering.

static constexpr int B_F4 = 32;  // 128 floats / 4 per row

__global__ void __launch_bounds__(256) prodlayer_kernel(
    const float4* __restrict__ node_mars,
    const float4* __restrict__ element_mars,
    const int*    __restrict__ nids,
    const int4*   __restrict__ cids,
    float4*       __restrict__ out,
    int n_prod)
{
    const int gwarp = (int)((blockIdx.x * (unsigned)blockDim.x + threadIdx.x) >> 5);
    const int lane  = threadIdx.x & 31;

    if (gwarp < n_prod) {
        const int4 c = __ldcs(&cids[gwarp]);      // streaming index read

        const float4 a = __ldg(&node_mars[(size_t)c.x * B_F4 + lane]);
        const float4 b = __ldg(&node_mars[(size_t)c.y * B_F4 + lane]);
        const float4 d = __ldg(&node_mars[(size_t)c.z * B_F4 + lane]);
        const float4 e = __ldg(&node_mars[(size_t)c.w * B_F4 + lane]);

        float4 s;
        s.x = (a.x + b.x) + (d.x + e.x);
        s.y = (a.y + b.y) + (d.y + e.y);
        s.z = (a.z + b.z) + (d.z + e.z);
        s.w = (a.w + b.w) + (d.w + e.w);

        const int o = __ldcs(&nids[gwarp]);
        __stcs(&out[(size_t)o * B_F4 + lane], s);  // evict-first streaming store
    } else if (gwarp == n_prod) {
        // Reserved row 0: out row 0 = element_mars row 0 (d_out is poisoned
        // to 0xAA before timing, so row 0 must be written explicitly).
        __stcs(&out[lane], __ldcs(&element_mars[lane]));
    }
}

extern "C" void kernel_launch(void* const* d_in, const int* in_sizes, int n_in,
                              void* d_out, int out_size)
{
    const float4* node_mars    = (const float4*)d_in[0];
    const float4* element_mars = (const float4*)d_in[1];
    const int*    nids         = (const int*)d_in[2];
    const int4*   cids         = (const int4*)d_in[3];
    float4*       out          = (float4*)d_out;

    const int n_prod  = in_sizes[2];          // 500000
    const int n_warps = n_prod + 1;           // +1 warp for the reserved row 0
    const int threads = 256;                  // 8 warps per block
    const int blocks  = (n_warps * 32 + threads - 1) / threads;

    prodlayer_kernel<<<blocks, threads>>>(node_mars, element_mars, nids, cids,
                                          out, n_prod);
}

// round 15
// speedup vs baseline: 1.0030x; 1.0030x over previous
#include <cuda_runtime.h>
#include <cstddef>

// ProdLayer forward: element_mars[nids] = node_mars[cids].sum(axis=1)
//   d_in[0] node_mars     float32  [N_SRC, 128]
//   d_in[1] element_mars  float32  [N_PROD+1, 128]
//   d_in[2] nids          int32    [N_PROD]
//   d_in[3] cids          int32    [N_PROD, 4]
// Output: float32 [N_PROD+1, 128]
//
// FINAL — converged after 14 rounds. Flat launch, warp-per-product,
// float4 lanes. __ldcs index reads + __stcs streaming stores (the one
// measurable policy win, ~-2%); plain __ldg for the 4 coalesced LDG.128
// gathers per lane.
//
// Roofline argument (why no further change can win):
//   traffic irreducibly ~1.13 GB =
//     443 MB compulsory gather reads (≈864K distinct rows x 512 B)
//   + ~420 MB re-reference misses — L2 hit rate is pinned at the
//     126MB/512MB capacity ratio, the statistical limit for a uniform-
//     random gather; no reorder beats it: sorting by one of 4 children
//     localizes only 25% of reads, per-child passes cost 4x RMW of the
//     256 MB output (+1.5 GB)
//   + 256 MB streaming writes + ~10 MB indices,
//   sustained at 6.8-6.9 TB/s = 86% of spec HBM (practical ceiling for
//   this 77/23 random-gather/streaming-store mix).
// Falsified R3-R14: column tiling (sector-tag amplification: 64 B/row
// slices still allocate 1M x 128 B line tags > L2), evict_last policies,
// L1 bypass, LDG.256, persistent grids at 47% and 92% occupancy (flat
// CTA replacement pipelines load issue for free; grid-stride serializes
// it), MLP 4 vs 8, CTA 128 vs 256, index-load reordering.

static constexpr int B_F4 = 32;  // 128 floats / 4 per row

__global__ void __launch_bounds__(256) prodlayer_kernel(
    const float4* __restrict__ node_mars,
    const float4* __restrict__ element_mars,
    const int*    __restrict__ nids,
    const int4*   __restrict__ cids,
    float4*       __restrict__ out,
    int n_prod)
{
    const int gwarp = (int)((blockIdx.x * (unsigned)blockDim.x + threadIdx.x) >> 5);
    const int lane  = threadIdx.x & 31;

    if (gwarp < n_prod) {
        const int4 c = __ldcs(&cids[gwarp]);      // streaming index read

        const float4 a = __ldg(&node_mars[(size_t)c.x * B_F4 + lane]);
        const float4 b = __ldg(&node_mars[(size_t)c.y * B_F4 + lane]);
        const float4 d = __ldg(&node_mars[(size_t)c.z * B_F4 + lane]);
        const float4 e = __ldg(&node_mars[(size_t)c.w * B_F4 + lane]);

        float4 s;
        s.x = (a.x + b.x) + (d.x + e.x);
        s.y = (a.y + b.y) + (d.y + e.y);
        s.z = (a.z + b.z) + (d.z + e.z);
        s.w = (a.w + b.w) + (d.w + e.w);

        const int o = __ldcs(&nids[gwarp]);
        __stcs(&out[(size_t)o * B_F4 + lane], s);  // evict-first streaming store
    } else if (gwarp == n_prod) {
        // Reserved row 0: out row 0 = element_mars row 0 (d_out is poisoned
        // to 0xAA before timing, so row 0 must be written explicitly).
        __stcs(&out[lane], __ldcs(&element_mars[lane]));
    }
}

extern "C" void kernel_launch(void* const* d_in, const int* in_sizes, int n_in,
                              void* d_out, int out_size)
{
    const float4* node_mars    = (const float4*)d_in[0];
    const float4* element_mars = (const float4*)d_in[1];
    const int*    nids         = (const int*)d_in[2];
    const int4*   cids         = (const int4*)d_in[3];
    float4*       out          = (float4*)d_out;

    const int n_prod  = in_sizes[2];          // 500000
    const int n_warps = n_prod + 1;           // +1 warp for the reserved row 0
    const int threads = 256;                  // 8 warps per block
    const int blocks  = (n_warps * 32 + threads - 1) / threads;

    prodlayer_kernel<<<blocks, threads>>>(node_mars, element_mars, nids, cids,
                                          out, n_prod);
}